// round 1
// baseline (speedup 1.0000x reference)
#include <cuda_runtime.h>

#define BATCH 2
#define SEQ   2048
#define CH    1024
#define NH    16
#define HSZ   64
#define MTOT  (BATCH*SEQ)     // 4096
#define QKVN  (3*CH)          // 3072
#define ATTN_SCALE 0.125f     // 64^-0.5

// Scratch: device globals (no cudaMalloc allowed)
static __device__ float g_q[(size_t)BATCH*NH*SEQ*HSZ];
static __device__ float g_k[(size_t)BATCH*NH*SEQ*HSZ];
static __device__ float g_v[(size_t)BATCH*NH*SEQ*HSZ];
static __device__ float g_attn[(size_t)MTOT*CH];

// ---------------------------------------------------------------------------
// QKV GEMM:  out(m,d) = sum_k x(m,k) * w_qkv(d,k)
// Epilogue scatters d -> (s = d%3, c = d/3, h = c>>6, hs = c&63)
// into g_q/g_k/g_v with layout [b][h][n][hs].
// ---------------------------------------------------------------------------
__global__ __launch_bounds__(256) void qkv_gemm_kernel(const float* __restrict__ A,
                                                       const float* __restrict__ W) {
    __shared__ float As[16][128];
    __shared__ float Bs[16][128];
    const int tid = threadIdx.x;
    const int m0 = blockIdx.y * 128;
    const int n0 = blockIdx.x * 128;
    const int ty = tid >> 4, tx = tid & 15;

    float acc[8][8];
#pragma unroll
    for (int i = 0; i < 8; ++i)
#pragma unroll
        for (int j = 0; j < 8; ++j) acc[i][j] = 0.f;

    for (int k0 = 0; k0 < CH; k0 += 16) {
#pragma unroll
        for (int p = 0; p < 2; ++p) {
            int id = tid + p * 256;
            int row = id >> 2, qq = id & 3;
            float4 av = *(const float4*)(A + (size_t)(m0 + row) * CH + k0 + qq * 4);
            As[qq*4+0][row] = av.x; As[qq*4+1][row] = av.y;
            As[qq*4+2][row] = av.z; As[qq*4+3][row] = av.w;
            float4 bv = *(const float4*)(W + (size_t)(n0 + row) * CH + k0 + qq * 4);
            Bs[qq*4+0][row] = bv.x; Bs[qq*4+1][row] = bv.y;
            Bs[qq*4+2][row] = bv.z; Bs[qq*4+3][row] = bv.w;
        }
        __syncthreads();
#pragma unroll
        for (int kk = 0; kk < 16; ++kk) {
            float a[8], b[8];
            *(float4*)(a)     = *(const float4*)&As[kk][ty*8];
            *(float4*)(a + 4) = *(const float4*)&As[kk][ty*8 + 4];
            *(float4*)(b)     = *(const float4*)&Bs[kk][tx*8];
            *(float4*)(b + 4) = *(const float4*)&Bs[kk][tx*8 + 4];
#pragma unroll
            for (int i = 0; i < 8; ++i)
#pragma unroll
                for (int j = 0; j < 8; ++j)
                    acc[i][j] = fmaf(a[i], b[j], acc[i][j]);
        }
        __syncthreads();
    }

#pragma unroll
    for (int i = 0; i < 8; ++i) {
        int m = m0 + ty * 8 + i;
        int b = m / SEQ, nn = m % SEQ;
#pragma unroll
        for (int j = 0; j < 8; ++j) {
            int d = n0 + tx * 8 + j;
            int s = d % 3, c = d / 3;
            int h = c >> 6, hs = c & 63;
            float* dst = (s == 0) ? g_q : (s == 1) ? g_k : g_v;
            dst[(((size_t)(b * NH + h)) * SEQ + nn) * HSZ + hs] = acc[i][j];
        }
    }
}

// ---------------------------------------------------------------------------
// Flash attention: one CTA = 64 query rows of one (b,h). 128 threads.
// KP smem tile holds K^T during the S-gemm, then is reused for P^T.
// ---------------------------------------------------------------------------
__global__ __launch_bounds__(128) void attn_kernel() {
    __shared__ float Qs[HSZ][64];   // Q^T tile: [hs][m]
    __shared__ float KP[64][64];    // K^T tile [hs][n], reused as P^T [n][m]
    __shared__ float Vs[64][HSZ];   // V tile: [n][hs]

    const int tid = threadIdx.x;
    const int bh = blockIdx.y;
    const int m0 = blockIdx.x * 64;
    const float* Qg = g_q + (size_t)bh * SEQ * HSZ;
    const float* Kg = g_k + (size_t)bh * SEQ * HSZ;
    const float* Vg = g_v + (size_t)bh * SEQ * HSZ;
    const int ty = tid >> 3, tx = tid & 7;  // 16 x 8 threads, 4x8 micro-tile

    // Load Q tile transposed
#pragma unroll
    for (int p = 0; p < 8; ++p) {
        int id = tid + p * 128;
        int row = id >> 4, qq = id & 15;
        float4 v = *(const float4*)(Qg + (size_t)(m0 + row) * HSZ + qq * 4);
        Qs[qq*4+0][row] = v.x; Qs[qq*4+1][row] = v.y;
        Qs[qq*4+2][row] = v.z; Qs[qq*4+3][row] = v.w;
    }

    float m_i[4], l_i[4], acc[4][8];
#pragma unroll
    for (int i = 0; i < 4; ++i) {
        m_i[i] = -1e30f; l_i[i] = 0.f;
#pragma unroll
        for (int j = 0; j < 8; ++j) acc[i][j] = 0.f;
    }

    for (int n0 = 0; n0 < SEQ; n0 += 64) {
        __syncthreads();  // previous iter done reading KP/Vs (also covers Qs on iter 0)
        // Load K (transposed) and V tiles
#pragma unroll
        for (int p = 0; p < 8; ++p) {
            int id = tid + p * 128;
            int row = id >> 4, qq = id & 15;
            float4 kv = *(const float4*)(Kg + (size_t)(n0 + row) * HSZ + qq * 4);
            KP[qq*4+0][row] = kv.x; KP[qq*4+1][row] = kv.y;
            KP[qq*4+2][row] = kv.z; KP[qq*4+3][row] = kv.w;
            *(float4*)&Vs[row][qq * 4] =
                *(const float4*)(Vg + (size_t)(n0 + row) * HSZ + qq * 4);
        }
        __syncthreads();

        // S = Q K^T  (4x8 per thread)
        float s[4][8];
#pragma unroll
        for (int i = 0; i < 4; ++i)
#pragma unroll
            for (int j = 0; j < 8; ++j) s[i][j] = 0.f;
#pragma unroll
        for (int kk = 0; kk < HSZ; ++kk) {
            float a[4], b[8];
            *(float4*)a       = *(const float4*)&Qs[kk][ty*4];
            *(float4*)b       = *(const float4*)&KP[kk][tx*8];
            *(float4*)(b + 4) = *(const float4*)&KP[kk][tx*8 + 4];
#pragma unroll
            for (int i = 0; i < 4; ++i)
#pragma unroll
                for (int j = 0; j < 8; ++j)
                    s[i][j] = fmaf(a[i], b[j], s[i][j]);
        }
        __syncthreads();  // everyone done reading K before we overwrite KP with P^T

        // Online softmax (row groups = 8 lanes sharing ty)
#pragma unroll
        for (int i = 0; i < 4; ++i) {
            float mloc = -1e30f;
#pragma unroll
            for (int j = 0; j < 8; ++j) {
                s[i][j] *= ATTN_SCALE;
                mloc = fmaxf(mloc, s[i][j]);
            }
            mloc = fmaxf(mloc, __shfl_xor_sync(0xffffffffu, mloc, 1));
            mloc = fmaxf(mloc, __shfl_xor_sync(0xffffffffu, mloc, 2));
            mloc = fmaxf(mloc, __shfl_xor_sync(0xffffffffu, mloc, 4));
            float mn = fmaxf(m_i[i], mloc);
            float alpha = __expf(m_i[i] - mn);
            m_i[i] = mn;
            float ls = 0.f;
#pragma unroll
            for (int j = 0; j < 8; ++j) {
                s[i][j] = __expf(s[i][j] - mn);
                ls += s[i][j];
            }
            ls += __shfl_xor_sync(0xffffffffu, ls, 1);
            ls += __shfl_xor_sync(0xffffffffu, ls, 2);
            ls += __shfl_xor_sync(0xffffffffu, ls, 4);
            l_i[i] = l_i[i] * alpha + ls;
#pragma unroll
            for (int j = 0; j < 8; ++j) acc[i][j] *= alpha;
        }
        // Write P^T into KP: KP[col][row]
#pragma unroll
        for (int j = 0; j < 8; ++j) {
            float4 w = make_float4(s[0][j], s[1][j], s[2][j], s[3][j]);
            *(float4*)&KP[tx*8 + j][ty*4] = w;
        }
        __syncthreads();

        // O += P V
#pragma unroll
        for (int kk = 0; kk < 64; ++kk) {
            float pr[4], vv[8];
            *(float4*)pr       = *(const float4*)&KP[kk][ty*4];
            *(float4*)vv       = *(const float4*)&Vs[kk][tx*8];
            *(float4*)(vv + 4) = *(const float4*)&Vs[kk][tx*8 + 4];
#pragma unroll
            for (int i = 0; i < 4; ++i)
#pragma unroll
                for (int j = 0; j < 8; ++j)
                    acc[i][j] = fmaf(pr[i], vv[j], acc[i][j]);
        }
    }

    // Normalize + write to g_attn in (B,N,C) layout (head transpose fused)
    const int b = bh / NH, h = bh % NH;
#pragma unroll
    for (int i = 0; i < 4; ++i) {
        float inv = 1.f / l_i[i];
        int row = m0 + ty * 4 + i;
#pragma unroll
        for (int j = 0; j < 8; ++j)
            g_attn[((size_t)(b * SEQ + row)) * CH + h * HSZ + tx * 8 + j] =
                acc[i][j] * inv;
    }
}

// ---------------------------------------------------------------------------
// Output projection: out = g_attn @ w_out^T + b_out
// ---------------------------------------------------------------------------
__global__ __launch_bounds__(256) void proj_gemm_kernel(const float* __restrict__ W,
                                                        const float* __restrict__ bias,
                                                        float* __restrict__ out) {
    __shared__ float As[16][128];
    __shared__ float Bs[16][128];
    const int tid = threadIdx.x;
    const int m0 = blockIdx.y * 128;
    const int n0 = blockIdx.x * 128;
    const int ty = tid >> 4, tx = tid & 15;

    float acc[8][8];
#pragma unroll
    for (int i = 0; i < 8; ++i)
#pragma unroll
        for (int j = 0; j < 8; ++j) acc[i][j] = 0.f;

    for (int k0 = 0; k0 < CH; k0 += 16) {
#pragma unroll
        for (int p = 0; p < 2; ++p) {
            int id = tid + p * 256;
            int row = id >> 2, qq = id & 3;
            float4 av = *(const float4*)(g_attn + (size_t)(m0 + row) * CH + k0 + qq * 4);
            As[qq*4+0][row] = av.x; As[qq*4+1][row] = av.y;
            As[qq*4+2][row] = av.z; As[qq*4+3][row] = av.w;
            float4 bv = *(const float4*)(W + (size_t)(n0 + row) * CH + k0 + qq * 4);
            Bs[qq*4+0][row] = bv.x; Bs[qq*4+1][row] = bv.y;
            Bs[qq*4+2][row] = bv.z; Bs[qq*4+3][row] = bv.w;
        }
        __syncthreads();
#pragma unroll
        for (int kk = 0; kk < 16; ++kk) {
            float a[8], b[8];
            *(float4*)(a)     = *(const float4*)&As[kk][ty*8];
            *(float4*)(a + 4) = *(const float4*)&As[kk][ty*8 + 4];
            *(float4*)(b)     = *(const float4*)&Bs[kk][tx*8];
            *(float4*)(b + 4) = *(const float4*)&Bs[kk][tx*8 + 4];
#pragma unroll
            for (int i = 0; i < 8; ++i)
#pragma unroll
                for (int j = 0; j < 8; ++j)
                    acc[i][j] = fmaf(a[i], b[j], acc[i][j]);
        }
        __syncthreads();
    }

#pragma unroll
    for (int i = 0; i < 8; ++i) {
        int m = m0 + ty * 8 + i;
#pragma unroll
        for (int j = 0; j < 8; ++j) {
            int n = n0 + tx * 8 + j;
            out[(size_t)m * CH + n] = acc[i][j] + bias[n];
        }
    }
}

extern "C" void kernel_launch(void* const* d_in, const int* in_sizes, int n_in,
                              void* d_out, int out_size) {
    const float* x     = (const float*)d_in[0];
    const float* w_qkv = (const float*)d_in[1];
    const float* w_out = (const float*)d_in[2];
    const float* b_out = (const float*)d_in[3];
    float* out = (float*)d_out;

    qkv_gemm_kernel<<<dim3(QKVN / 128, MTOT / 128), 256>>>(x, w_qkv);
    attn_kernel<<<dim3(SEQ / 64, BATCH * NH), 128>>>();
    proj_gemm_kernel<<<dim3(CH / 128, MTOT / 128), 256>>>(w_out, b_out, out);
}

// round 3
// speedup vs baseline: 1.3857x; 1.3857x over previous
#include <cuda_runtime.h>
#include <cstdint>

#define BATCH 2
#define SEQ   2048
#define CH    1024
#define NH    16
#define HSZ   64
#define MTOT  (BATCH*SEQ)     // 4096
#define ATTN_SCALE 0.125f
#define SK    36              // smem row stride (floats) -> conflict-free frags

// Scratch: device globals (no cudaMalloc allowed)
static __device__ float g_q[(size_t)BATCH*NH*SEQ*HSZ];
static __device__ float g_k[(size_t)BATCH*NH*SEQ*HSZ];
static __device__ float g_v[(size_t)BATCH*NH*SEQ*HSZ];
static __device__ float g_attn[(size_t)MTOT*CH];

static __device__ __forceinline__ uint32_t f2tf32(float v) {
    uint32_t r;
    asm("cvt.rna.tf32.f32 %0, %1;" : "=r"(r) : "f"(v));
    return r;
}

static __device__ __forceinline__ void mma8(float* c, const uint32_t* a,
                                            uint32_t b0, uint32_t b1) {
    asm volatile(
        "mma.sync.aligned.m16n8k8.row.col.f32.tf32.tf32.f32 "
        "{%0,%1,%2,%3},{%4,%5,%6,%7},{%8,%9},{%0,%1,%2,%3};"
        : "+f"(c[0]), "+f"(c[1]), "+f"(c[2]), "+f"(c[3])
        : "r"(a[0]), "r"(a[1]), "r"(a[2]), "r"(a[3]), "r"(b0), "r"(b1));
}

// ---------------------------------------------------------------------------
// QKV GEMM (tf32 mma.sync): D[128x96] = x[128,1024] . w_qkv^T slice
// 96 columns = half of one head's interleaved q/k/v -> clean de-interleave.
// ---------------------------------------------------------------------------
#define QKV_SMEM ((2*128*SK + 2*96*SK) * 4)   // 64512 B
__global__ __launch_bounds__(256, 2) void qkv_tc(const float* __restrict__ A,
                                                 const float* __restrict__ W) {
    extern __shared__ __align__(16) float sm[];
    uint32_t* sAu = (uint32_t*)sm;                 // 2 bufs x 128*SK
    uint32_t* sBu = (uint32_t*)sm + 2 * 128 * SK;  // 2 bufs x 96*SK

    const int tid = threadIdx.x, warp = tid >> 5, lane = tid & 31;
    const int wm = warp >> 1, wn = warp & 1;
    const int g = lane >> 2, t = lane & 3;
    const int m0 = blockIdx.y * 128;
    const int bx = blockIdx.x;
    const int n0 = bx * 96;

    float acc[2][6][4];
#pragma unroll
    for (int i = 0; i < 2; ++i)
#pragma unroll
        for (int j = 0; j < 6; ++j)
#pragma unroll
            for (int q = 0; q < 4; ++q) acc[i][j][q] = 0.f;

    float4 ar[4], br[3];

    auto LDG = [&](int c) {
        const int k0 = 32 * c;
#pragma unroll
        for (int p = 0; p < 4; ++p) {
            int idx = tid + 256 * p, r = idx >> 3, q = idx & 7;
            ar[p] = *(const float4*)(A + (size_t)(m0 + r) * CH + k0 + 4 * q);
        }
#pragma unroll
        for (int p = 0; p < 3; ++p) {
            int idx = tid + 256 * p, r = idx >> 3, q = idx & 7;
            br[p] = *(const float4*)(W + (size_t)(n0 + r) * CH + k0 + 4 * q);
        }
    };
    auto STS = [&](int buf) {
#pragma unroll
        for (int p = 0; p < 4; ++p) {
            int idx = tid + 256 * p, r = idx >> 3, q = idx & 7;
            uint32_t* d = sAu + buf * 128 * SK + r * SK + 4 * q;
            d[0] = f2tf32(ar[p].x); d[1] = f2tf32(ar[p].y);
            d[2] = f2tf32(ar[p].z); d[3] = f2tf32(ar[p].w);
        }
#pragma unroll
        for (int p = 0; p < 3; ++p) {
            int idx = tid + 256 * p, r = idx >> 3, q = idx & 7;
            uint32_t* d = sBu + buf * 96 * SK + r * SK + 4 * q;
            d[0] = f2tf32(br[p].x); d[1] = f2tf32(br[p].y);
            d[2] = f2tf32(br[p].z); d[3] = f2tf32(br[p].w);
        }
    };

    LDG(0); STS(0); __syncthreads();

    for (int c = 0; c < 32; ++c) {
        const int buf = c & 1;
        if (c < 31) LDG(c + 1);
        const uint32_t* bA = sAu + buf * 128 * SK;
        const uint32_t* bB = sBu + buf * 96 * SK;
#pragma unroll
        for (int s = 0; s < 4; ++s) {
            uint32_t afr[2][4];
#pragma unroll
            for (int mi = 0; mi < 2; ++mi) {
                const uint32_t* pa = bA + (wm * 32 + mi * 16 + g) * SK + s * 8 + t;
                afr[mi][0] = pa[0];
                afr[mi][1] = pa[8 * SK];
                afr[mi][2] = pa[4];
                afr[mi][3] = pa[8 * SK + 4];
            }
#pragma unroll
            for (int nj = 0; nj < 6; ++nj) {
                const uint32_t* pb = bB + (wn * 48 + nj * 8 + g) * SK + s * 8 + t;
                uint32_t b0 = pb[0], b1 = pb[4];
                mma8(acc[0][nj], afr[0], b0, b1);
                mma8(acc[1][nj], afr[1], b0, b1);
            }
        }
        if (c < 31) STS(buf ^ 1);
        __syncthreads();
    }

    // Epilogue: stage D[128x96] in smem (stride 100), then coalesced scatter.
    float* Ds = sm;
#pragma unroll
    for (int mi = 0; mi < 2; ++mi)
#pragma unroll
        for (int nj = 0; nj < 6; ++nj) {
            int row = wm * 32 + mi * 16 + g;
            int col = wn * 48 + nj * 8 + 2 * t;
            *(float2*)(Ds + row * 100 + col) =
                make_float2(acc[mi][nj][0], acc[mi][nj][1]);
            *(float2*)(Ds + (row + 8) * 100 + col) =
                make_float2(acc[mi][nj][2], acc[mi][nj][3]);
        }
    __syncthreads();

    const int h = bx >> 1, hs0 = (bx & 1) * 32;
#pragma unroll
    for (int p = 0; p < 12; ++p) {
        int id = tid + 256 * p;       // 0..3071 = 128 rows x 3 s x 8 c4-groups
        int c4 = id & 7;
        int s = (id >> 3) % 3;
        int row = id / 24;
        int m = m0 + row;
        int bb = m >> 11, nn = m & 2047;
        float* dst = (s == 0) ? g_q : (s == 1) ? g_k : g_v;
        const float* Dr = Ds + row * 100 + 12 * c4 + s;
        float4 o = make_float4(Dr[0], Dr[3], Dr[6], Dr[9]);
        *(float4*)(dst + ((size_t)(bb * NH + h) * SEQ + nn) * HSZ + hs0 + 4 * c4) = o;
    }
}

// ---------------------------------------------------------------------------
// Output projection (tf32 mma.sync): out[128x128] = g_attn . w_out^T + bias
// ---------------------------------------------------------------------------
#define PROJ_SMEM (4*128*SK * 4)   // 73728 B
__global__ __launch_bounds__(256, 2) void proj_tc(const float* __restrict__ W,
                                                  const float* __restrict__ bias,
                                                  float* __restrict__ out) {
    extern __shared__ __align__(16) float sm[];
    uint32_t* sAu = (uint32_t*)sm;
    uint32_t* sBu = (uint32_t*)sm + 2 * 128 * SK;

    const int tid = threadIdx.x, warp = tid >> 5, lane = tid & 31;
    const int wm = warp >> 1, wn = warp & 1;
    const int g = lane >> 2, t = lane & 3;
    const int m0 = blockIdx.y * 128;
    const int n0 = blockIdx.x * 128;

    float acc[2][8][4];
#pragma unroll
    for (int i = 0; i < 2; ++i)
#pragma unroll
        for (int j = 0; j < 8; ++j)
#pragma unroll
            for (int q = 0; q < 4; ++q) acc[i][j][q] = 0.f;

    float4 ar[4], br[4];

    auto LDG = [&](int c) {
        const int k0 = 32 * c;
#pragma unroll
        for (int p = 0; p < 4; ++p) {
            int idx = tid + 256 * p, r = idx >> 3, q = idx & 7;
            ar[p] = *(const float4*)(g_attn + (size_t)(m0 + r) * CH + k0 + 4 * q);
            br[p] = *(const float4*)(W + (size_t)(n0 + r) * CH + k0 + 4 * q);
        }
    };
    auto STS = [&](int buf) {
#pragma unroll
        for (int p = 0; p < 4; ++p) {
            int idx = tid + 256 * p, r = idx >> 3, q = idx & 7;
            uint32_t* dA = sAu + buf * 128 * SK + r * SK + 4 * q;
            dA[0] = f2tf32(ar[p].x); dA[1] = f2tf32(ar[p].y);
            dA[2] = f2tf32(ar[p].z); dA[3] = f2tf32(ar[p].w);
            uint32_t* dB = sBu + buf * 128 * SK + r * SK + 4 * q;
            dB[0] = f2tf32(br[p].x); dB[1] = f2tf32(br[p].y);
            dB[2] = f2tf32(br[p].z); dB[3] = f2tf32(br[p].w);
        }
    };

    LDG(0); STS(0); __syncthreads();

    for (int c = 0; c < 32; ++c) {
        const int buf = c & 1;
        if (c < 31) LDG(c + 1);
        const uint32_t* bA = sAu + buf * 128 * SK;
        const uint32_t* bB = sBu + buf * 128 * SK;
#pragma unroll
        for (int s = 0; s < 4; ++s) {
            uint32_t afr[2][4];
#pragma unroll
            for (int mi = 0; mi < 2; ++mi) {
                const uint32_t* pa = bA + (wm * 32 + mi * 16 + g) * SK + s * 8 + t;
                afr[mi][0] = pa[0];
                afr[mi][1] = pa[8 * SK];
                afr[mi][2] = pa[4];
                afr[mi][3] = pa[8 * SK + 4];
            }
#pragma unroll
            for (int nj = 0; nj < 8; ++nj) {
                const uint32_t* pb = bB + (wn * 64 + nj * 8 + g) * SK + s * 8 + t;
                uint32_t b0 = pb[0], b1 = pb[4];
                mma8(acc[0][nj], afr[0], b0, b1);
                mma8(acc[1][nj], afr[1], b0, b1);
            }
        }
        if (c < 31) STS(buf ^ 1);
        __syncthreads();
    }

#pragma unroll
    for (int mi = 0; mi < 2; ++mi)
#pragma unroll
        for (int nj = 0; nj < 8; ++nj) {
            int row = m0 + wm * 32 + mi * 16 + g;
            int col = n0 + wn * 64 + nj * 8 + 2 * t;
            float b0 = __ldg(bias + col), b1 = __ldg(bias + col + 1);
            *(float2*)(out + (size_t)row * CH + col) =
                make_float2(acc[mi][nj][0] + b0, acc[mi][nj][1] + b1);
            *(float2*)(out + (size_t)(row + 8) * CH + col) =
                make_float2(acc[mi][nj][2] + b0, acc[mi][nj][3] + b1);
        }
}

// ---------------------------------------------------------------------------
// Flash attention (unchanged SIMT fp32, round-1 verified)
// ---------------------------------------------------------------------------
__global__ __launch_bounds__(128) void attn_kernel() {
    __shared__ float Qs[HSZ][64];
    __shared__ float KP[64][64];
    __shared__ float Vs[64][HSZ];

    const int tid = threadIdx.x;
    const int bh = blockIdx.y;
    const int m0 = blockIdx.x * 64;
    const float* Qg = g_q + (size_t)bh * SEQ * HSZ;
    const float* Kg = g_k + (size_t)bh * SEQ * HSZ;
    const float* Vg = g_v + (size_t)bh * SEQ * HSZ;
    const int ty = tid >> 3, tx = tid & 7;

#pragma unroll
    for (int p = 0; p < 8; ++p) {
        int id = tid + p * 128;
        int row = id >> 4, qq = id & 15;
        float4 v = *(const float4*)(Qg + (size_t)(m0 + row) * HSZ + qq * 4);
        Qs[qq*4+0][row] = v.x; Qs[qq*4+1][row] = v.y;
        Qs[qq*4+2][row] = v.z; Qs[qq*4+3][row] = v.w;
    }

    float m_i[4], l_i[4], acc[4][8];
#pragma unroll
    for (int i = 0; i < 4; ++i) {
        m_i[i] = -1e30f; l_i[i] = 0.f;
#pragma unroll
        for (int j = 0; j < 8; ++j) acc[i][j] = 0.f;
    }

    for (int n0 = 0; n0 < SEQ; n0 += 64) {
        __syncthreads();
#pragma unroll
        for (int p = 0; p < 8; ++p) {
            int id = tid + p * 128;
            int row = id >> 4, qq = id & 15;
            float4 kv = *(const float4*)(Kg + (size_t)(n0 + row) * HSZ + qq * 4);
            KP[qq*4+0][row] = kv.x; KP[qq*4+1][row] = kv.y;
            KP[qq*4+2][row] = kv.z; KP[qq*4+3][row] = kv.w;
            *(float4*)&Vs[row][qq * 4] =
                *(const float4*)(Vg + (size_t)(n0 + row) * HSZ + qq * 4);
        }
        __syncthreads();

        float s[4][8];
#pragma unroll
        for (int i = 0; i < 4; ++i)
#pragma unroll
            for (int j = 0; j < 8; ++j) s[i][j] = 0.f;
#pragma unroll
        for (int kk = 0; kk < HSZ; ++kk) {
            float a[4], b[8];
            *(float4*)a       = *(const float4*)&Qs[kk][ty*4];
            *(float4*)b       = *(const float4*)&KP[kk][tx*8];
            *(float4*)(b + 4) = *(const float4*)&KP[kk][tx*8 + 4];
#pragma unroll
            for (int i = 0; i < 4; ++i)
#pragma unroll
                for (int j = 0; j < 8; ++j)
                    s[i][j] = fmaf(a[i], b[j], s[i][j]);
        }
        __syncthreads();

#pragma unroll
        for (int i = 0; i < 4; ++i) {
            float mloc = -1e30f;
#pragma unroll
            for (int j = 0; j < 8; ++j) {
                s[i][j] *= ATTN_SCALE;
                mloc = fmaxf(mloc, s[i][j]);
            }
            mloc = fmaxf(mloc, __shfl_xor_sync(0xffffffffu, mloc, 1));
            mloc = fmaxf(mloc, __shfl_xor_sync(0xffffffffu, mloc, 2));
            mloc = fmaxf(mloc, __shfl_xor_sync(0xffffffffu, mloc, 4));
            float mn = fmaxf(m_i[i], mloc);
            float alpha = __expf(m_i[i] - mn);
            m_i[i] = mn;
            float ls = 0.f;
#pragma unroll
            for (int j = 0; j < 8; ++j) {
                s[i][j] = __expf(s[i][j] - mn);
                ls += s[i][j];
            }
            ls += __shfl_xor_sync(0xffffffffu, ls, 1);
            ls += __shfl_xor_sync(0xffffffffu, ls, 2);
            ls += __shfl_xor_sync(0xffffffffu, ls, 4);
            l_i[i] = l_i[i] * alpha + ls;
#pragma unroll
            for (int j = 0; j < 8; ++j) acc[i][j] *= alpha;
        }
#pragma unroll
        for (int j = 0; j < 8; ++j) {
            float4 w = make_float4(s[0][j], s[1][j], s[2][j], s[3][j]);
            *(float4*)&KP[tx*8 + j][ty*4] = w;
        }
        __syncthreads();

#pragma unroll
        for (int kk = 0; kk < 64; ++kk) {
            float pr[4], vv[8];
            *(float4*)pr       = *(const float4*)&KP[kk][ty*4];
            *(float4*)vv       = *(const float4*)&Vs[kk][tx*8];
            *(float4*)(vv + 4) = *(const float4*)&Vs[kk][tx*8 + 4];
#pragma unroll
            for (int i = 0; i < 4; ++i)
#pragma unroll
                for (int j = 0; j < 8; ++j)
                    acc[i][j] = fmaf(pr[i], vv[j], acc[i][j]);
        }
    }

    const int b = bh / NH, h = bh % NH;
#pragma unroll
    for (int i = 0; i < 4; ++i) {
        float inv = 1.f / l_i[i];
        int row = m0 + ty * 4 + i;
#pragma unroll
        for (int j = 0; j < 8; ++j)
            g_attn[((size_t)(b * SEQ + row)) * CH + h * HSZ + tx * 8 + j] =
                acc[i][j] * inv;
    }
}

extern "C" void kernel_launch(void* const* d_in, const int* in_sizes, int n_in,
                              void* d_out, int out_size) {
    const float* x     = (const float*)d_in[0];
    const float* w_qkv = (const float*)d_in[1];
    const float* w_out = (const float*)d_in[2];
    const float* b_out = (const float*)d_in[3];
    float* out = (float*)d_out;

    cudaFuncSetAttribute(qkv_tc, cudaFuncAttributeMaxDynamicSharedMemorySize, QKV_SMEM);
    cudaFuncSetAttribute(proj_tc, cudaFuncAttributeMaxDynamicSharedMemorySize, PROJ_SMEM);

    qkv_tc<<<dim3(32, 32), 256, QKV_SMEM>>>(x, w_qkv);
    attn_kernel<<<dim3(SEQ / 64, BATCH * NH), 128>>>();
    proj_tc<<<dim3(CH / 128, MTOT / 128), 256, PROJ_SMEM>>>(w_out, b_out, out);
}

// round 4
// speedup vs baseline: 3.7091x; 2.6768x over previous
#include <cuda_runtime.h>
#include <cstdint>

#define BATCH 2
#define SEQ   2048
#define CH    1024
#define NH    16
#define HSZ   64
#define MTOT  (BATCH*SEQ)     // 4096
#define ATTN_SCALE 0.125f
#define SK    36              // smem row stride (floats) -> conflict-free frags

// Scratch: device globals (no cudaMalloc allowed)
static __device__ float g_q[(size_t)BATCH*NH*SEQ*HSZ];
static __device__ float g_k[(size_t)BATCH*NH*SEQ*HSZ];
static __device__ float g_v[(size_t)BATCH*NH*SEQ*HSZ];
static __device__ float g_attn[(size_t)MTOT*CH];

static __device__ __forceinline__ uint32_t f2tf32(float v) {
    uint32_t r;
    asm("cvt.rna.tf32.f32 %0, %1;" : "=r"(r) : "f"(v));
    return r;
}

static __device__ __forceinline__ void mma8(float* c, const uint32_t* a,
                                            uint32_t b0, uint32_t b1) {
    asm volatile(
        "mma.sync.aligned.m16n8k8.row.col.f32.tf32.tf32.f32 "
        "{%0,%1,%2,%3},{%4,%5,%6,%7},{%8,%9},{%0,%1,%2,%3};"
        : "+f"(c[0]), "+f"(c[1]), "+f"(c[2]), "+f"(c[3])
        : "r"(a[0]), "r"(a[1]), "r"(a[2]), "r"(a[3]), "r"(b0), "r"(b1));
}

// ---------------------------------------------------------------------------
// QKV GEMM (tf32 mma.sync): D[128x96] = x[128,1024] . w_qkv^T slice
// ---------------------------------------------------------------------------
#define QKV_SMEM ((2*128*SK + 2*96*SK) * 4)   // 64512 B
__global__ __launch_bounds__(256, 2) void qkv_tc(const float* __restrict__ A,
                                                 const float* __restrict__ W) {
    extern __shared__ __align__(16) float sm[];
    uint32_t* sAu = (uint32_t*)sm;
    uint32_t* sBu = (uint32_t*)sm + 2 * 128 * SK;

    const int tid = threadIdx.x, warp = tid >> 5, lane = tid & 31;
    const int wm = warp >> 1, wn = warp & 1;
    const int g = lane >> 2, t = lane & 3;
    const int m0 = blockIdx.y * 128;
    const int bx = blockIdx.x;
    const int n0 = bx * 96;

    float acc[2][6][4];
#pragma unroll
    for (int i = 0; i < 2; ++i)
#pragma unroll
        for (int j = 0; j < 6; ++j)
#pragma unroll
            for (int q = 0; q < 4; ++q) acc[i][j][q] = 0.f;

    float4 ar[4], br[3];

    auto LDG = [&](int c) {
        const int k0 = 32 * c;
#pragma unroll
        for (int p = 0; p < 4; ++p) {
            int idx = tid + 256 * p, r = idx >> 3, q = idx & 7;
            ar[p] = *(const float4*)(A + (size_t)(m0 + r) * CH + k0 + 4 * q);
        }
#pragma unroll
        for (int p = 0; p < 3; ++p) {
            int idx = tid + 256 * p, r = idx >> 3, q = idx & 7;
            br[p] = *(const float4*)(W + (size_t)(n0 + r) * CH + k0 + 4 * q);
        }
    };
    auto STS = [&](int buf) {
#pragma unroll
        for (int p = 0; p < 4; ++p) {
            int idx = tid + 256 * p, r = idx >> 3, q = idx & 7;
            uint32_t* d = sAu + buf * 128 * SK + r * SK + 4 * q;
            d[0] = f2tf32(ar[p].x); d[1] = f2tf32(ar[p].y);
            d[2] = f2tf32(ar[p].z); d[3] = f2tf32(ar[p].w);
        }
#pragma unroll
        for (int p = 0; p < 3; ++p) {
            int idx = tid + 256 * p, r = idx >> 3, q = idx & 7;
            uint32_t* d = sBu + buf * 96 * SK + r * SK + 4 * q;
            d[0] = f2tf32(br[p].x); d[1] = f2tf32(br[p].y);
            d[2] = f2tf32(br[p].z); d[3] = f2tf32(br[p].w);
        }
    };

    LDG(0); STS(0); __syncthreads();

    for (int c = 0; c < 32; ++c) {
        const int buf = c & 1;
        if (c < 31) LDG(c + 1);
        const uint32_t* bA = sAu + buf * 128 * SK;
        const uint32_t* bB = sBu + buf * 96 * SK;
#pragma unroll
        for (int s = 0; s < 4; ++s) {
            uint32_t afr[2][4];
#pragma unroll
            for (int mi = 0; mi < 2; ++mi) {
                const uint32_t* pa = bA + (wm * 32 + mi * 16 + g) * SK + s * 8 + t;
                afr[mi][0] = pa[0];
                afr[mi][1] = pa[8 * SK];
                afr[mi][2] = pa[4];
                afr[mi][3] = pa[8 * SK + 4];
            }
#pragma unroll
            for (int nj = 0; nj < 6; ++nj) {
                const uint32_t* pb = bB + (wn * 48 + nj * 8 + g) * SK + s * 8 + t;
                uint32_t b0 = pb[0], b1 = pb[4];
                mma8(acc[0][nj], afr[0], b0, b1);
                mma8(acc[1][nj], afr[1], b0, b1);
            }
        }
        if (c < 31) STS(buf ^ 1);
        __syncthreads();
    }

    float* Ds = sm;
#pragma unroll
    for (int mi = 0; mi < 2; ++mi)
#pragma unroll
        for (int nj = 0; nj < 6; ++nj) {
            int row = wm * 32 + mi * 16 + g;
            int col = wn * 48 + nj * 8 + 2 * t;
            *(float2*)(Ds + row * 100 + col) =
                make_float2(acc[mi][nj][0], acc[mi][nj][1]);
            *(float2*)(Ds + (row + 8) * 100 + col) =
                make_float2(acc[mi][nj][2], acc[mi][nj][3]);
        }
    __syncthreads();

    const int h = bx >> 1, hs0 = (bx & 1) * 32;
#pragma unroll
    for (int p = 0; p < 12; ++p) {
        int id = tid + 256 * p;
        int c4 = id & 7;
        int s = (id >> 3) % 3;
        int row = id / 24;
        int m = m0 + row;
        int bb = m >> 11, nn = m & 2047;
        float* dst = (s == 0) ? g_q : (s == 1) ? g_k : g_v;
        const float* Dr = Ds + row * 100 + 12 * c4 + s;
        float4 o = make_float4(Dr[0], Dr[3], Dr[6], Dr[9]);
        *(float4*)(dst + ((size_t)(bb * NH + h) * SEQ + nn) * HSZ + hs0 + 4 * c4) = o;
    }
}

// ---------------------------------------------------------------------------
// Flash attention (tf32 mma.sync): CTA = 128 query rows x one (b,h)
// 8 warps x 16 rows. S and PV both on tensor pipe.
// ---------------------------------------------------------------------------
#define ASTR 68
#define ATTN_SMEM ((128*ASTR + 64*ASTR + 64*ASTR + 128*ASTR) * 4)  // 104448 B
__global__ __launch_bounds__(256, 2) void attn_tc() {
    extern __shared__ __align__(16) float sm[];
    uint32_t* Qs = (uint32_t*)sm;              // [128][ASTR] Q (pre-scaled)
    uint32_t* Ks = Qs + 128 * ASTR;            // [64][ASTR]  K natural [key][hs]
    uint32_t* Vs = Ks + 64 * ASTR;             // [64][ASTR]  V natural [key][hs]
    uint32_t* Ps = Vs + 64 * ASTR;             // [128][ASTR] P [row][key]

    const int tid = threadIdx.x, warp = tid >> 5, lane = tid & 31;
    const int g = lane >> 2, t = lane & 3;
    const int bh = blockIdx.y;
    const int m0 = blockIdx.x * 128;
    const int wrow = warp * 16;
    const float* Qg = g_q + (size_t)bh * SEQ * HSZ;
    const float* Kg = g_k + (size_t)bh * SEQ * HSZ;
    const float* Vg = g_v + (size_t)bh * SEQ * HSZ;

    // Load Q tile (scale folded in; x0.125 is exact)
#pragma unroll
    for (int p = 0; p < 8; ++p) {
        int idx = tid + 256 * p;
        int r = idx >> 4, q = idx & 15;
        float4 v = *(const float4*)(Qg + (size_t)(m0 + r) * HSZ + 4 * q);
        uint32_t* d = Qs + r * ASTR + 4 * q;
        d[0] = f2tf32(v.x * ATTN_SCALE); d[1] = f2tf32(v.y * ATTN_SCALE);
        d[2] = f2tf32(v.z * ATTN_SCALE); d[3] = f2tf32(v.w * ATTN_SCALE);
    }

    float m_i[2] = {-1e30f, -1e30f};
    float l_i[2] = {0.f, 0.f};
    float acc_o[8][4];
#pragma unroll
    for (int nj = 0; nj < 8; ++nj)
#pragma unroll
        for (int q = 0; q < 4; ++q) acc_o[nj][q] = 0.f;

    for (int n0 = 0; n0 < SEQ; n0 += 64) {
        __syncthreads();   // prior compute done reading Ks/Vs (covers Qs on it 0)
#pragma unroll
        for (int p = 0; p < 4; ++p) {
            int idx = tid + 256 * p;
            int r = idx >> 4, q = idx & 15;
            float4 kv = *(const float4*)(Kg + (size_t)(n0 + r) * HSZ + 4 * q);
            uint32_t* dk = Ks + r * ASTR + 4 * q;
            dk[0] = f2tf32(kv.x); dk[1] = f2tf32(kv.y);
            dk[2] = f2tf32(kv.z); dk[3] = f2tf32(kv.w);
            float4 vv = *(const float4*)(Vg + (size_t)(n0 + r) * HSZ + 4 * q);
            uint32_t* dv = Vs + r * ASTR + 4 * q;
            dv[0] = f2tf32(vv.x); dv[1] = f2tf32(vv.y);
            dv[2] = f2tf32(vv.z); dv[3] = f2tf32(vv.w);
        }
        __syncthreads();

        // S = Q.K^T  (warp: 16 x 64)
        float s[8][4];
#pragma unroll
        for (int nj = 0; nj < 8; ++nj)
#pragma unroll
            for (int q = 0; q < 4; ++q) s[nj][q] = 0.f;
#pragma unroll
        for (int ks = 0; ks < 8; ++ks) {
            uint32_t afr[4];
            const uint32_t* pa = Qs + (wrow + g) * ASTR + ks * 8 + t;
            afr[0] = pa[0];
            afr[1] = pa[8 * ASTR];
            afr[2] = pa[4];
            afr[3] = pa[8 * ASTR + 4];
#pragma unroll
            for (int nj = 0; nj < 8; ++nj) {
                const uint32_t* pb = Ks + (nj * 8 + g) * ASTR + ks * 8 + t;
                mma8(s[nj], afr, pb[0], pb[4]);
            }
        }

        // Online softmax on fragment rows (g and g+8)
        float mx0 = -1e30f, mx1 = -1e30f;
#pragma unroll
        for (int nj = 0; nj < 8; ++nj) {
            mx0 = fmaxf(mx0, fmaxf(s[nj][0], s[nj][1]));
            mx1 = fmaxf(mx1, fmaxf(s[nj][2], s[nj][3]));
        }
        mx0 = fmaxf(mx0, __shfl_xor_sync(0xffffffffu, mx0, 1));
        mx0 = fmaxf(mx0, __shfl_xor_sync(0xffffffffu, mx0, 2));
        mx1 = fmaxf(mx1, __shfl_xor_sync(0xffffffffu, mx1, 1));
        mx1 = fmaxf(mx1, __shfl_xor_sync(0xffffffffu, mx1, 2));
        float mn0 = fmaxf(m_i[0], mx0), mn1 = fmaxf(m_i[1], mx1);
        float a0 = __expf(m_i[0] - mn0), a1 = __expf(m_i[1] - mn1);
        m_i[0] = mn0; m_i[1] = mn1;
        float s0 = 0.f, s1 = 0.f;
#pragma unroll
        for (int nj = 0; nj < 8; ++nj) {
            s[nj][0] = __expf(s[nj][0] - mn0);
            s[nj][1] = __expf(s[nj][1] - mn0);
            s[nj][2] = __expf(s[nj][2] - mn1);
            s[nj][3] = __expf(s[nj][3] - mn1);
            s0 += s[nj][0] + s[nj][1];
            s1 += s[nj][2] + s[nj][3];
        }
        s0 += __shfl_xor_sync(0xffffffffu, s0, 1);
        s0 += __shfl_xor_sync(0xffffffffu, s0, 2);
        s1 += __shfl_xor_sync(0xffffffffu, s1, 1);
        s1 += __shfl_xor_sync(0xffffffffu, s1, 2);
        l_i[0] = l_i[0] * a0 + s0;
        l_i[1] = l_i[1] * a1 + s1;
#pragma unroll
        for (int nj = 0; nj < 8; ++nj) {
            acc_o[nj][0] *= a0; acc_o[nj][1] *= a0;
            acc_o[nj][2] *= a1; acc_o[nj][3] *= a1;
        }

        // Stage P (per-warp private rows -> only warp-level sync needed)
        uint32_t* pr0 = Ps + (wrow + g) * ASTR + 2 * t;
        uint32_t* pr1 = Ps + (wrow + g + 8) * ASTR + 2 * t;
#pragma unroll
        for (int nj = 0; nj < 8; ++nj) {
            uint2 w0 = make_uint2(f2tf32(s[nj][0]), f2tf32(s[nj][1]));
            uint2 w1 = make_uint2(f2tf32(s[nj][2]), f2tf32(s[nj][3]));
            *(uint2*)(pr0 + nj * 8) = w0;
            *(uint2*)(pr1 + nj * 8) = w1;
        }
        __syncwarp();

        // O += P.V  (B-frag = transposed read of natural V tile)
#pragma unroll
        for (int ks = 0; ks < 8; ++ks) {
            uint32_t afr[4];
            const uint32_t* pa = Ps + (wrow + g) * ASTR + ks * 8 + t;
            afr[0] = pa[0];
            afr[1] = pa[8 * ASTR];
            afr[2] = pa[4];
            afr[3] = pa[8 * ASTR + 4];
            const uint32_t* vb0 = Vs + (ks * 8 + t) * ASTR + g;
            const uint32_t* vb1 = Vs + (ks * 8 + t + 4) * ASTR + g;
#pragma unroll
            for (int nj = 0; nj < 8; ++nj)
                mma8(acc_o[nj], afr, vb0[nj * 8], vb1[nj * 8]);
        }
    }

    // Epilogue: normalize + write (B,N,C) with head offset
    const int b = bh >> 4, h = bh & 15;
    const float inv0 = 1.f / l_i[0], inv1 = 1.f / l_i[1];
    const int r0 = m0 + wrow + g, r1 = r0 + 8;
#pragma unroll
    for (int nj = 0; nj < 8; ++nj) {
        int col = h * HSZ + nj * 8 + 2 * t;
        *(float2*)(g_attn + ((size_t)(b * SEQ + r0)) * CH + col) =
            make_float2(acc_o[nj][0] * inv0, acc_o[nj][1] * inv0);
        *(float2*)(g_attn + ((size_t)(b * SEQ + r1)) * CH + col) =
            make_float2(acc_o[nj][2] * inv1, acc_o[nj][3] * inv1);
    }
}

// ---------------------------------------------------------------------------
// Output projection (tf32 mma.sync): out[128x128] = g_attn . w_out^T + bias
// ---------------------------------------------------------------------------
#define PROJ_SMEM (4*128*SK * 4)   // 73728 B
__global__ __launch_bounds__(256, 2) void proj_tc(const float* __restrict__ W,
                                                  const float* __restrict__ bias,
                                                  float* __restrict__ out) {
    extern __shared__ __align__(16) float sm[];
    uint32_t* sAu = (uint32_t*)sm;
    uint32_t* sBu = (uint32_t*)sm + 2 * 128 * SK;

    const int tid = threadIdx.x, warp = tid >> 5, lane = tid & 31;
    const int wm = warp >> 1, wn = warp & 1;
    const int g = lane >> 2, t = lane & 3;
    const int m0 = blockIdx.y * 128;
    const int n0 = blockIdx.x * 128;

    float acc[2][8][4];
#pragma unroll
    for (int i = 0; i < 2; ++i)
#pragma unroll
        for (int j = 0; j < 8; ++j)
#pragma unroll
            for (int q = 0; q < 4; ++q) acc[i][j][q] = 0.f;

    float4 ar[4], br[4];

    auto LDG = [&](int c) {
        const int k0 = 32 * c;
#pragma unroll
        for (int p = 0; p < 4; ++p) {
            int idx = tid + 256 * p, r = idx >> 3, q = idx & 7;
            ar[p] = *(const float4*)(g_attn + (size_t)(m0 + r) * CH + k0 + 4 * q);
            br[p] = *(const float4*)(W + (size_t)(n0 + r) * CH + k0 + 4 * q);
        }
    };
    auto STS = [&](int buf) {
#pragma unroll
        for (int p = 0; p < 4; ++p) {
            int idx = tid + 256 * p, r = idx >> 3, q = idx & 7;
            uint32_t* dA = sAu + buf * 128 * SK + r * SK + 4 * q;
            dA[0] = f2tf32(ar[p].x); dA[1] = f2tf32(ar[p].y);
            dA[2] = f2tf32(ar[p].z); dA[3] = f2tf32(ar[p].w);
            uint32_t* dB = sBu + buf * 128 * SK + r * SK + 4 * q;
            dB[0] = f2tf32(br[p].x); dB[1] = f2tf32(br[p].y);
            dB[2] = f2tf32(br[p].z); dB[3] = f2tf32(br[p].w);
        }
    };

    LDG(0); STS(0); __syncthreads();

    for (int c = 0; c < 32; ++c) {
        const int buf = c & 1;
        if (c < 31) LDG(c + 1);
        const uint32_t* bA = sAu + buf * 128 * SK;
        const uint32_t* bB = sBu + buf * 128 * SK;
#pragma unroll
        for (int s = 0; s < 4; ++s) {
            uint32_t afr[2][4];
#pragma unroll
            for (int mi = 0; mi < 2; ++mi) {
                const uint32_t* pa = bA + (wm * 32 + mi * 16 + g) * SK + s * 8 + t;
                afr[mi][0] = pa[0];
                afr[mi][1] = pa[8 * SK];
                afr[mi][2] = pa[4];
                afr[mi][3] = pa[8 * SK + 4];
            }
#pragma unroll
            for (int nj = 0; nj < 8; ++nj) {
                const uint32_t* pb = bB + (wn * 64 + nj * 8 + g) * SK + s * 8 + t;
                uint32_t b0 = pb[0], b1 = pb[4];
                mma8(acc[0][nj], afr[0], b0, b1);
                mma8(acc[1][nj], afr[1], b0, b1);
            }
        }
        if (c < 31) STS(buf ^ 1);
        __syncthreads();
    }

#pragma unroll
    for (int mi = 0; mi < 2; ++mi)
#pragma unroll
        for (int nj = 0; nj < 8; ++nj) {
            int row = m0 + wm * 32 + mi * 16 + g;
            int col = n0 + wn * 64 + nj * 8 + 2 * t;
            float b0 = __ldg(bias + col), b1 = __ldg(bias + col + 1);
            *(float2*)(out + (size_t)row * CH + col) =
                make_float2(acc[mi][nj][0] + b0, acc[mi][nj][1] + b1);
            *(float2*)(out + (size_t)(row + 8) * CH + col) =
                make_float2(acc[mi][nj][2] + b0, acc[mi][nj][3] + b1);
        }
}

extern "C" void kernel_launch(void* const* d_in, const int* in_sizes, int n_in,
                              void* d_out, int out_size) {
    const float* x     = (const float*)d_in[0];
    const float* w_qkv = (const float*)d_in[1];
    const float* w_out = (const float*)d_in[2];
    const float* b_out = (const float*)d_in[3];
    float* out = (float*)d_out;

    cudaFuncSetAttribute(qkv_tc, cudaFuncAttributeMaxDynamicSharedMemorySize, QKV_SMEM);
    cudaFuncSetAttribute(attn_tc, cudaFuncAttributeMaxDynamicSharedMemorySize, ATTN_SMEM);
    cudaFuncSetAttribute(proj_tc, cudaFuncAttributeMaxDynamicSharedMemorySize, PROJ_SMEM);

    qkv_tc<<<dim3(32, 32), 256, QKV_SMEM>>>(x, w_qkv);
    attn_tc<<<dim3(SEQ / 128, BATCH * NH), 256, ATTN_SMEM>>>();
    proj_tc<<<dim3(CH / 128, MTOT / 128), 256, PROJ_SMEM>>>(w_out, b_out, out);
}